// round 3
// baseline (speedup 1.0000x reference)
#include <cuda_runtime.h>
#include <cuda_bf16.h>

// ---------------------------------------------------------------------------
// ASymplecticR4_NN on GB300 without tcgen05 (harness PTX targets compute_103,
// so only arch-neutral mma.sync is available).
//
// Per-element TinyMLP (2->32->32->1) forward + analytic input gradient:
//   out[i] = { x1 + dF/dy1, x2 + dF/dy2, y1, y2 }
//
// Each warp owns an m16 tile (16 elements). Both 32x32 matvecs run as
// mma.sync.m16n8k16 bf16 with register-resident weight fragments. All
// activations live in registers in MMA fragment layout; the accumulator
// layout of one MMA is bit-compatible with the A-fragment layout of the
// next, so there is no shared-memory staging and no synchronization at all.
// ---------------------------------------------------------------------------

#define NTHREADS 128

static __device__ __forceinline__ float sigm(float x) {
    float t;
    asm("tanh.approx.f32 %0, %1;" : "=f"(t) : "f"(x * 0.5f));
    return fmaf(t, 0.5f, 0.5f);
}

static __device__ __forceinline__ unsigned packbf(float lo, float hi) {
    __nv_bfloat162 b = __floats2bfloat162_rn(lo, hi);
    return *reinterpret_cast<unsigned*>(&b);
}

// D = A * B + C   (m16n8k16, bf16 in, f32 accum, A row-major, B col-major)
static __device__ __forceinline__ void mma16816(float* d, const unsigned* a,
                                                const unsigned* b, const float* c) {
    asm volatile(
        "mma.sync.aligned.m16n8k16.row.col.f32.bf16.bf16.f32 "
        "{%0,%1,%2,%3}, {%4,%5,%6,%7}, {%8,%9}, {%10,%11,%12,%13};"
        : "=f"(d[0]), "=f"(d[1]), "=f"(d[2]), "=f"(d[3])
        : "r"(a[0]), "r"(a[1]), "r"(a[2]), "r"(a[3]),
          "r"(b[0]), "r"(b[1]),
          "f"(c[0]), "f"(c[1]), "f"(c[2]), "f"(c[3]));
}

__global__ void __launch_bounds__(NTHREADS)
mlp_grad_kernel(const float* __restrict__ x1, const float* __restrict__ x2,
                const float* __restrict__ y1, const float* __restrict__ y2,
                const float* __restrict__ W1, const float* __restrict__ b1,
                const float* __restrict__ W2, const float* __restrict__ b2,
                const float* __restrict__ W3, float* __restrict__ out,
                int n, int ntiles) {
    const int tid = threadIdx.x;
    const int wid = tid >> 5;
    const int lane = tid & 31;
    const int tg = lane & 3;        // thread-in-quad -> column pair selector
    const int qr = lane >> 2;       // quad row 0..7

    // ------------------------------------------------------------------
    // Per-thread constants in fragment layout.
    // Column set owned by this thread: col(j,p) = 8*j + 2*tg + p, j=0..3,p=0..1
    // ------------------------------------------------------------------
    float w10[8], w11[8], b1v[8], b2v[8], w3v[8];
#pragma unroll
    for (int j = 0; j < 4; j++) {
#pragma unroll
        for (int p = 0; p < 2; p++) {
            int col = 8 * j + 2 * tg + p;
            w10[2 * j + p] = W1[col];        // W1[0][col]
            w11[2 * j + p] = W1[32 + col];   // W1[1][col]
            b1v[2 * j + p] = b1[col];
            b2v[2 * j + p] = b2[col];
            w3v[2 * j + p] = W3[col];
        }
    }

    // Weight B-fragments (k16n8, col-major thread mapping):
    //   b0 packs (k0, n),(k0+1, n);  b1 packs (k0+8, n),(k0+9, n)
    //   with n = 8*j + qr, k0 = 16*f + 2*tg.
    // MMA1: pre2 = h1 @ W2        -> B[k][n] = W2[k*32 + n]
    // MMA2: d1   = g2 @ W2^T      -> B[k][n] = W2[n*32 + k]
    unsigned B1[4][2][2], B2[4][2][2];
#pragma unroll
    for (int j = 0; j < 4; j++) {
#pragma unroll
        for (int f = 0; f < 2; f++) {
            int nn = 8 * j + qr;
            int k0 = 16 * f + 2 * tg;
            B1[j][f][0] = packbf(W2[k0 * 32 + nn], W2[(k0 + 1) * 32 + nn]);
            B1[j][f][1] = packbf(W2[(k0 + 8) * 32 + nn], W2[(k0 + 9) * 32 + nn]);
            B2[j][f][0] = packbf(W2[nn * 32 + k0], W2[nn * 32 + k0 + 1]);
            B2[j][f][1] = packbf(W2[nn * 32 + k0 + 8], W2[nn * 32 + k0 + 9]);
        }
    }

    const int warps_per_cta = NTHREADS / 32;
    const int total_warps = gridDim.x * warps_per_cta;
    const int gw = blockIdx.x * warps_per_cta + wid;

    for (int tile = gw; tile < ntiles; tile += total_warps) {
        const int base = tile * 16;
        const int r0 = base + qr;       // first row this thread covers
        const int r1 = base + qr + 8;   // second row
        const int r0c = min(r0, n - 1);
        const int r1c = min(r1, n - 1);

        const float y1a = y1[r0c], y1b = y1[r1c];
        const float y2a = y2[r0c], y2b = y2[r1c];

        // ---- layer 1 (fragment layout): h1[s][2j+p], s=0 -> r0, s=1 -> r1 ----
        float h1f[2][8];
#pragma unroll
        for (int q = 0; q < 8; q++) {
            float p0 = fmaf(y1a, w10[q], fmaf(y2a, w11[q], b1v[q]));
            float p1 = fmaf(y1b, w10[q], fmaf(y2b, w11[q], b1v[q]));
            h1f[0][q] = sigm(p0);
            h1f[1][q] = sigm(p1);
        }

        // A-frag for MMA1: frag f covers k = 16f + {2tg,2tg+1} (j=2f) and +8 (j=2f+1)
        unsigned A[2][4];
#pragma unroll
        for (int f = 0; f < 2; f++) {
            A[f][0] = packbf(h1f[0][4 * f + 0], h1f[0][4 * f + 1]);
            A[f][1] = packbf(h1f[1][4 * f + 0], h1f[1][4 * f + 1]);
            A[f][2] = packbf(h1f[0][4 * f + 2], h1f[0][4 * f + 3]);
            A[f][3] = packbf(h1f[1][4 * f + 2], h1f[1][4 * f + 3]);
        }

        // ---- MMA1: pre2 = h1 @ W2 + b2 (b2 folded into initial accum) ----
        float d[4][4];
#pragma unroll
        for (int j = 0; j < 4; j++) {
            float c0[4] = {b2v[2 * j], b2v[2 * j + 1], b2v[2 * j], b2v[2 * j + 1]};
            mma16816(d[j], A[0], B1[j][0], c0);
            mma16816(d[j], A[1], B1[j][1], d[j]);
        }

        // ---- layer 2 elementwise: h2 = sigm(pre2); g2 = h2(1-h2)*W3 ----
        // accum reg -> (s, pair): d[j][0]=(s0,p0) d[j][1]=(s0,p1) d[j][2]=(s1,p0) d[j][3]=(s1,p1)
        float g2f[2][8];
#pragma unroll
        for (int j = 0; j < 4; j++) {
#pragma unroll
            for (int p = 0; p < 2; p++) {
                float h2a = sigm(d[j][p]);
                float h2b = sigm(d[j][2 + p]);
                float ta = h2a * w3v[2 * j + p];
                float tb = h2b * w3v[2 * j + p];
                g2f[0][2 * j + p] = fmaf(-h2a, ta, ta);  // h2(1-h2)w3
                g2f[1][2 * j + p] = fmaf(-h2b, tb, tb);
            }
        }

#pragma unroll
        for (int f = 0; f < 2; f++) {
            A[f][0] = packbf(g2f[0][4 * f + 0], g2f[0][4 * f + 1]);
            A[f][1] = packbf(g2f[1][4 * f + 0], g2f[1][4 * f + 1]);
            A[f][2] = packbf(g2f[0][4 * f + 2], g2f[0][4 * f + 3]);
            A[f][3] = packbf(g2f[1][4 * f + 2], g2f[1][4 * f + 3]);
        }

        // ---- MMA2: d1 = g2 @ W2^T ----
        const float zz[4] = {0.0f, 0.0f, 0.0f, 0.0f};
#pragma unroll
        for (int j = 0; j < 4; j++) {
            mma16816(d[j], A[0], B2[j][0], zz);
            mma16816(d[j], A[1], B2[j][1], d[j]);
        }

        // ---- dY = W1 @ (d1 * h1 * (1 - h1)), partial over this thread's 8 cols ----
        float dY0a = 0.0f, dY1a = 0.0f, dY0b = 0.0f, dY1b = 0.0f;
#pragma unroll
        for (int j = 0; j < 4; j++) {
#pragma unroll
            for (int p = 0; p < 2; p++) {
                int q = 2 * j + p;
                float ha = h1f[0][q];
                float hb = h1f[1][q];
                float dpa = d[j][p] * (ha * (1.0f - ha));
                float dpb = d[j][2 + p] * (hb * (1.0f - hb));
                dY0a = fmaf(w10[q], dpa, dY0a);
                dY1a = fmaf(w11[q], dpa, dY1a);
                dY0b = fmaf(w10[q], dpb, dY0b);
                dY1b = fmaf(w11[q], dpb, dY1b);
            }
        }
        // reduce across the quad (lanes tg=0..3 hold disjoint column subsets)
#pragma unroll
        for (int m = 1; m <= 2; m <<= 1) {
            dY0a += __shfl_xor_sync(0xffffffffu, dY0a, m);
            dY1a += __shfl_xor_sync(0xffffffffu, dY1a, m);
            dY0b += __shfl_xor_sync(0xffffffffu, dY0b, m);
            dY1b += __shfl_xor_sync(0xffffffffu, dY1b, m);
        }

        if (tg == 0) {
            if (r0 < n) {
                float4 o;
                o.x = x1[r0] + dY0a;
                o.y = x2[r0] + dY1a;
                o.z = y1a;
                o.w = y2a;
                reinterpret_cast<float4*>(out)[r0] = o;
            }
            if (r1 < n) {
                float4 o;
                o.x = x1[r1] + dY0b;
                o.y = x2[r1] + dY1b;
                o.z = y1b;
                o.w = y2b;
                reinterpret_cast<float4*>(out)[r1] = o;
            }
        }
    }
}

extern "C" void kernel_launch(void* const* d_in, const int* in_sizes, int n_in,
                              void* d_out, int out_size) {
    const float* x1 = (const float*)d_in[0];
    const float* x2 = (const float*)d_in[1];
    const float* y1 = (const float*)d_in[2];
    const float* y2 = (const float*)d_in[3];
    const float* W1 = (const float*)d_in[4];
    const float* b1 = (const float*)d_in[5];
    const float* W2 = (const float*)d_in[6];
    const float* b2 = (const float*)d_in[7];
    const float* W3 = (const float*)d_in[8];
    float* out = (float*)d_out;

    int n = in_sizes[0];
    int ntiles = (n + 15) / 16;

    int per_sm = 0;
    cudaOccupancyMaxActiveBlocksPerMultiprocessor(&per_sm, mlp_grad_kernel,
                                                  NTHREADS, 0);
    if (per_sm < 1) per_sm = 1;
    int sms = 0;
    cudaDeviceGetAttribute(&sms, cudaDevAttrMultiProcessorCount, 0);
    if (sms <= 0) sms = 148;

    int grid = per_sm * sms;
    int max_grid = (ntiles + (NTHREADS / 32) - 1) / (NTHREADS / 32);
    if (grid > max_grid) grid = max_grid;

    mlp_grad_kernel<<<grid, NTHREADS>>>(x1, x2, y1, y2, W1, b1, W2, b2, W3, out,
                                        n, ntiles);
}

// round 8
// speedup vs baseline: 1.3938x; 1.3938x over previous
#include <cuda_runtime.h>
#include <cuda_bf16.h>

// ---------------------------------------------------------------------------
// ASymplecticR4_NN: TinyMLP (2->32->32->1) forward + analytic input gradient.
//   out[i] = { x1 + dF/dy1, x2 + dF/dy2, y1, y2 }
//
// mma.sync.m16n8k16 bf16 (arch-neutral; harness PTX targets compute_103, no
// tcgen05). One warp = 16 elements. Three MMAs per tile:
//   MMA1: 0.5*(h1 @ W2)          (0.5 folded into B1 for the sigmoid scale)
//   MMA2: d1 = g2 @ W2^T
//   MMA3: dY = dp @ W1^T  (N=8, 2 live cols; x1/x2 ride in the accumulator,
//         result lands on the tg==0 store lanes -> no shuffles)
// All elementwise math packed bf16x2 (HFMA2 + tanh.approx.bf16x2), fragment
// layouts chained register-to-register; zero smem, zero barriers.
// ---------------------------------------------------------------------------

#define NTHREADS 128

static __device__ __forceinline__ unsigned packbf(float lo, float hi) {
    __nv_bfloat162 b = __floats2bfloat162_rn(lo, hi);
    return *reinterpret_cast<unsigned*>(&b);
}

// pack two f32 into bf16x2: low half = lo, high half = hi
static __device__ __forceinline__ unsigned cvtpack(float lo, float hi) {
    unsigned r;
    asm("cvt.rn.bf16x2.f32 %0, %1, %2;" : "=r"(r) : "f"(hi), "f"(lo));
    return r;
}

static __device__ __forceinline__ unsigned tanh2(unsigned x) {
    unsigned r;
    asm("tanh.approx.bf16x2 %0, %1;" : "=r"(r) : "r"(x));
    return r;
}

static __device__ __forceinline__ __nv_bfloat162 U2B(unsigned u) {
    return *reinterpret_cast<__nv_bfloat162*>(&u);
}
static __device__ __forceinline__ unsigned B2U(__nv_bfloat162 b) {
    return *reinterpret_cast<unsigned*>(&b);
}
static __device__ __forceinline__ unsigned bfma2(unsigned a, unsigned b, unsigned c) {
    return B2U(__hfma2(U2B(a), U2B(b), U2B(c)));
}
static __device__ __forceinline__ unsigned bmul2(unsigned a, unsigned b) {
    return B2U(__hmul2(U2B(a), U2B(b)));
}
static __device__ __forceinline__ unsigned badd2(unsigned a, unsigned b) {
    return B2U(__hadd2(U2B(a), U2B(b)));
}
static __device__ __forceinline__ unsigned bneg2(unsigned a) {
    return B2U(__hneg2(U2B(a)));
}

// D = A * B + C   (m16n8k16, bf16 in, f32 accum, A row-major, B col-major)
static __device__ __forceinline__ void mma16816(float* d, const unsigned* a,
                                                const unsigned* b, const float* c) {
    asm volatile(
        "mma.sync.aligned.m16n8k16.row.col.f32.bf16.bf16.f32 "
        "{%0,%1,%2,%3}, {%4,%5,%6,%7}, {%8,%9}, {%10,%11,%12,%13};"
        : "=f"(d[0]), "=f"(d[1]), "=f"(d[2]), "=f"(d[3])
        : "r"(a[0]), "r"(a[1]), "r"(a[2]), "r"(a[3]),
          "r"(b[0]), "r"(b[1]),
          "f"(c[0]), "f"(c[1]), "f"(c[2]), "f"(c[3]));
}

__global__ void __launch_bounds__(NTHREADS, 5)
mlp_grad_kernel(const float* __restrict__ x1, const float* __restrict__ x2,
                const float* __restrict__ y1, const float* __restrict__ y2,
                const float* __restrict__ W1, const float* __restrict__ b1,
                const float* __restrict__ W2, const float* __restrict__ b2,
                const float* __restrict__ W3, float* __restrict__ out,
                int n, int ntiles) {
    const int tid = threadIdx.x;
    const int wid = tid >> 5;
    const int lane = tid & 31;
    const int tg = lane & 3;        // thread-in-quad -> column-pair selector
    const int qr = lane >> 2;       // quad row 0..7

    const unsigned h05 = packbf(0.5f, 0.5f);

    // ---- per-thread constants, packed bf16x2 in fragment layout ----
    // pair j covers cols (8j + 2tg, 8j + 2tg + 1)
    unsigned w10p[4], w11p[4], b1p[4], b2p[4], w3p[4];
#pragma unroll
    for (int j = 0; j < 4; j++) {
        int c0 = 8 * j + 2 * tg;
        w10p[j] = packbf(0.5f * W1[c0], 0.5f * W1[c0 + 1]);
        w11p[j] = packbf(0.5f * W1[32 + c0], 0.5f * W1[32 + c0 + 1]);
        b1p[j]  = packbf(0.5f * b1[c0], 0.5f * b1[c0 + 1]);
        b2p[j]  = packbf(0.5f * b2[c0], 0.5f * b2[c0 + 1]);
        w3p[j]  = packbf(W3[c0], W3[c0 + 1]);
    }

    // Weight B-fragments (k16n8 col-major): thread holds n = 8j+qr,
    // b0 = (k0, k0+1), b1 = (k0+8, k0+9), k0 = 16f + 2tg.
    // B1 = 0.5*W2 (sigmoid half-scale folded in; exact exponent shift)
    // B2 = W2^T
    unsigned B1[4][2][2], B2[4][2][2];
#pragma unroll
    for (int j = 0; j < 4; j++) {
#pragma unroll
        for (int f = 0; f < 2; f++) {
            int nn = 8 * j + qr;
            int k0 = 16 * f + 2 * tg;
            B1[j][f][0] = packbf(0.5f * W2[k0 * 32 + nn], 0.5f * W2[(k0 + 1) * 32 + nn]);
            B1[j][f][1] = packbf(0.5f * W2[(k0 + 8) * 32 + nn], 0.5f * W2[(k0 + 9) * 32 + nn]);
            B2[j][f][0] = packbf(W2[nn * 32 + k0], W2[nn * 32 + k0 + 1]);
            B2[j][f][1] = packbf(W2[nn * 32 + k0 + 8], W2[nn * 32 + k0 + 9]);
        }
    }
    // B3 = W1^T for MMA3 (dY): n = qr; only n<2 are live columns.
    unsigned B3[2][2];
#pragma unroll
    for (int f = 0; f < 2; f++) {
        int k0 = 16 * f + 2 * tg;
        if (qr < 2) {
            B3[f][0] = packbf(W1[qr * 32 + k0], W1[qr * 32 + k0 + 1]);
            B3[f][1] = packbf(W1[qr * 32 + k0 + 8], W1[qr * 32 + k0 + 9]);
        } else {
            B3[f][0] = 0u;
            B3[f][1] = 0u;
        }
    }

    const int warps_per_cta = NTHREADS / 32;
    const int total_warps = gridDim.x * warps_per_cta;
    const int gw = blockIdx.x * warps_per_cta + wid;
    const float zz[4] = {0.0f, 0.0f, 0.0f, 0.0f};

    for (int tile = gw; tile < ntiles; tile += total_warps) {
        const int base = tile * 16;
        const int r0 = base + qr;
        const int r1 = base + qr + 8;
        const int r0c = min(r0, n - 1);
        const int r1c = min(r1, n - 1);

        // ---- layer 1 (packed): halfpre = 0.5*(y1*W1_0 + y2*W1_1 + b1) ----
        const unsigned y1pa = cvtpack(y1[r0c], y1[r0c]);
        const unsigned y2pa = cvtpack(y2[r0c], y2[r0c]);
        const unsigned y1pb = cvtpack(y1[r1c], y1[r1c]);
        const unsigned y2pb = cvtpack(y2[r1c], y2[r1c]);

        unsigned h[2][4];   // h1, packed pairs, [s][j]
#pragma unroll
        for (int j = 0; j < 4; j++) {
            unsigned p0 = bfma2(y1pa, w10p[j], bfma2(y2pa, w11p[j], b1p[j]));
            unsigned p1 = bfma2(y1pb, w10p[j], bfma2(y2pb, w11p[j], b1p[j]));
            h[0][j] = bfma2(tanh2(p0), h05, h05);
            h[1][j] = bfma2(tanh2(p1), h05, h05);
        }

        // ---- MMA1: d = 0.5 * (h1 @ W2) ----
        unsigned a0[4] = {h[0][0], h[1][0], h[0][1], h[1][1]};
        unsigned a1[4] = {h[0][2], h[1][2], h[0][3], h[1][3]};
        float d[4][4];
#pragma unroll
        for (int j = 0; j < 4; j++) {
            mma16816(d[j], a0, B1[j][0], zz);
            mma16816(d[j], a1, B1[j][1], d[j]);
        }

        // ---- layer 2 elementwise: h2 = sigm(pre2); g2 = h2*(1-h2)*W3 ----
        unsigned g[2][4];
#pragma unroll
        for (int j = 0; j < 4; j++) {
#pragma unroll
            for (int s = 0; s < 2; s++) {
                unsigned pr = badd2(cvtpack(d[j][2 * s], d[j][2 * s + 1]), b2p[j]);
                unsigned h2 = bfma2(tanh2(pr), h05, h05);
                unsigned tm = bmul2(h2, w3p[j]);
                g[s][j] = bfma2(bneg2(h2), tm, tm);
            }
        }

        // ---- MMA2: d1 = g2 @ W2^T ----
        unsigned ga0[4] = {g[0][0], g[1][0], g[0][1], g[1][1]};
        unsigned ga1[4] = {g[0][2], g[1][2], g[0][3], g[1][3]};
#pragma unroll
        for (int j = 0; j < 4; j++) {
            mma16816(d[j], ga0, B2[j][0], zz);
            mma16816(d[j], ga1, B2[j][1], d[j]);
        }

        // ---- dp = d1 * h1 * (1 - h1), packed ----
        unsigned dp[2][4];
#pragma unroll
        for (int j = 0; j < 4; j++) {
#pragma unroll
            for (int s = 0; s < 2; s++) {
                unsigned hp = bfma2(bneg2(h[s][j]), h[s][j], h[s][j]);
                dp[s][j] = bmul2(cvtpack(d[j][2 * s], d[j][2 * s + 1]), hp);
            }
        }

        // ---- MMA3: dY = dp @ W1^T, accumulator seeded with x1/x2 ----
        unsigned da0[4] = {dp[0][0], dp[1][0], dp[0][1], dp[1][1]};
        unsigned da1[4] = {dp[0][2], dp[1][2], dp[0][3], dp[1][3]};
        float cx[4] = {0.0f, 0.0f, 0.0f, 0.0f};
        if (tg == 0) {
            cx[0] = x1[r0c];
            cx[1] = x2[r0c];
            cx[2] = x1[r1c];
            cx[3] = x2[r1c];
        }
        float d3[4];
        mma16816(d3, da0, B3[0], cx);
        mma16816(d3, da1, B3[1], d3);

        // ---- store: lanes tg==0 hold cols 0,1 = (x+dY0, x+dY1) ----
        if (tg == 0) {
            if (r0 < n) {
                float4 o;
                o.x = d3[0];
                o.y = d3[1];
                o.z = y1[r0];
                o.w = y2[r0];
                reinterpret_cast<float4*>(out)[r0] = o;
            }
            if (r1 < n) {
                float4 o;
                o.x = d3[2];
                o.y = d3[3];
                o.z = y1[r1];
                o.w = y2[r1];
                reinterpret_cast<float4*>(out)[r1] = o;
            }
        }
    }
}

extern "C" void kernel_launch(void* const* d_in, const int* in_sizes, int n_in,
                              void* d_out, int out_size) {
    const float* x1 = (const float*)d_in[0];
    const float* x2 = (const float*)d_in[1];
    const float* y1 = (const float*)d_in[2];
    const float* y2 = (const float*)d_in[3];
    const float* W1 = (const float*)d_in[4];
    const float* b1 = (const float*)d_in[5];
    const float* W2 = (const float*)d_in[6];
    const float* b2 = (const float*)d_in[7];
    const float* W3 = (const float*)d_in[8];
    float* out = (float*)d_out;

    int n = in_sizes[0];
    int ntiles = (n + 15) / 16;

    int per_sm = 0;
    cudaOccupancyMaxActiveBlocksPerMultiprocessor(&per_sm, mlp_grad_kernel,
                                                  NTHREADS, 0);
    if (per_sm < 1) per_sm = 1;
    int sms = 0;
    cudaDeviceGetAttribute(&sms, cudaDevAttrMultiProcessorCount, 0);
    if (sms <= 0) sms = 148;

    int grid = per_sm * sms;
    int max_grid = (ntiles + (NTHREADS / 32) - 1) / (NTHREADS / 32);
    if (grid > max_grid) grid = max_grid;

    mlp_grad_kernel<<<grid, NTHREADS>>>(x1, x2, y1, y2, W1, b1, W2, b2, W3, out,
                                        n, ntiles);
}

// round 11
// speedup vs baseline: 1.5900x; 1.1408x over previous
#include <cuda_runtime.h>
#include <cuda_bf16.h>

// ---------------------------------------------------------------------------
// ASymplecticR4_NN: TinyMLP (2->32->32->1) forward + analytic input gradient.
//   out[i] = { x1 + dF/dy1, x2 + dF/dy2, y1, y2 }
//
// mma.sync.m16n8k16 bf16 fragment-chained pipeline (no smem, no barriers).
// Round 9: 2-way ILP — each warp runs TWO independent 16-element tiles per
// iteration, stage-interleaved, to cover the serial fragment-chain latency
// that left issue_active at 47%.
// ---------------------------------------------------------------------------

#define NTHREADS 128

static __device__ __forceinline__ unsigned packbf(float lo, float hi) {
    __nv_bfloat162 b = __floats2bfloat162_rn(lo, hi);
    return *reinterpret_cast<unsigned*>(&b);
}

// pack two f32 into bf16x2: low half = lo, high half = hi
static __device__ __forceinline__ unsigned cvtpack(float lo, float hi) {
    unsigned r;
    asm("cvt.rn.bf16x2.f32 %0, %1, %2;" : "=r"(r) : "f"(hi), "f"(lo));
    return r;
}

static __device__ __forceinline__ unsigned tanh2(unsigned x) {
    unsigned r;
    asm("tanh.approx.bf16x2 %0, %1;" : "=r"(r) : "r"(x));
    return r;
}

static __device__ __forceinline__ __nv_bfloat162 U2B(unsigned u) {
    return *reinterpret_cast<__nv_bfloat162*>(&u);
}
static __device__ __forceinline__ unsigned B2U(__nv_bfloat162 b) {
    return *reinterpret_cast<unsigned*>(&b);
}
static __device__ __forceinline__ unsigned bfma2(unsigned a, unsigned b, unsigned c) {
    return B2U(__hfma2(U2B(a), U2B(b), U2B(c)));
}
static __device__ __forceinline__ unsigned bmul2(unsigned a, unsigned b) {
    return B2U(__hmul2(U2B(a), U2B(b)));
}
static __device__ __forceinline__ unsigned badd2(unsigned a, unsigned b) {
    return B2U(__hadd2(U2B(a), U2B(b)));
}
static __device__ __forceinline__ unsigned bneg2(unsigned a) {
    return B2U(__hneg2(U2B(a)));
}

// D = A * B + C   (m16n8k16, bf16 in, f32 accum, A row-major, B col-major)
static __device__ __forceinline__ void mma16816(float* d, const unsigned* a,
                                                const unsigned* b, const float* c) {
    asm volatile(
        "mma.sync.aligned.m16n8k16.row.col.f32.bf16.bf16.f32 "
        "{%0,%1,%2,%3}, {%4,%5,%6,%7}, {%8,%9}, {%10,%11,%12,%13};"
        : "=f"(d[0]), "=f"(d[1]), "=f"(d[2]), "=f"(d[3])
        : "r"(a[0]), "r"(a[1]), "r"(a[2]), "r"(a[3]),
          "r"(b[0]), "r"(b[1]),
          "f"(c[0]), "f"(c[1]), "f"(c[2]), "f"(c[3]));
}

__global__ void __launch_bounds__(NTHREADS, 4)
mlp_grad_kernel(const float* __restrict__ x1, const float* __restrict__ x2,
                const float* __restrict__ y1, const float* __restrict__ y2,
                const float* __restrict__ W1, const float* __restrict__ b1,
                const float* __restrict__ W2, const float* __restrict__ b2,
                const float* __restrict__ W3, float* __restrict__ out,
                int n, int npairs) {
    const int tid = threadIdx.x;
    const int wid = tid >> 5;
    const int lane = tid & 31;
    const int tg = lane & 3;        // thread-in-quad -> column-pair selector
    const int qr = lane >> 2;       // quad row 0..7

    const unsigned h05 = packbf(0.5f, 0.5f);

    // ---- per-thread constants, packed bf16x2 in fragment layout ----
    unsigned w10p[4], w11p[4], b1p[4], b2p[4], w3p[4];
#pragma unroll
    for (int j = 0; j < 4; j++) {
        int c0 = 8 * j + 2 * tg;
        w10p[j] = packbf(0.5f * W1[c0], 0.5f * W1[c0 + 1]);
        w11p[j] = packbf(0.5f * W1[32 + c0], 0.5f * W1[32 + c0 + 1]);
        b1p[j]  = packbf(0.5f * b1[c0], 0.5f * b1[c0 + 1]);
        b2p[j]  = packbf(0.5f * b2[c0], 0.5f * b2[c0 + 1]);
        w3p[j]  = packbf(W3[c0], W3[c0 + 1]);
    }

    // Weight B-fragments: B1 = 0.5*W2 (K-major), B2 = W2^T
    unsigned B1[4][2][2], B2[4][2][2];
#pragma unroll
    for (int j = 0; j < 4; j++) {
#pragma unroll
        for (int f = 0; f < 2; f++) {
            int nn = 8 * j + qr;
            int k0 = 16 * f + 2 * tg;
            B1[j][f][0] = packbf(0.5f * W2[k0 * 32 + nn], 0.5f * W2[(k0 + 1) * 32 + nn]);
            B1[j][f][1] = packbf(0.5f * W2[(k0 + 8) * 32 + nn], 0.5f * W2[(k0 + 9) * 32 + nn]);
            B2[j][f][0] = packbf(W2[nn * 32 + k0], W2[nn * 32 + k0 + 1]);
            B2[j][f][1] = packbf(W2[nn * 32 + k0 + 8], W2[nn * 32 + k0 + 9]);
        }
    }
    // B3 = W1^T for MMA3 (dY): n = qr; only n<2 live.
    unsigned B3[2][2];
#pragma unroll
    for (int f = 0; f < 2; f++) {
        int k0 = 16 * f + 2 * tg;
        if (qr < 2) {
            B3[f][0] = packbf(W1[qr * 32 + k0], W1[qr * 32 + k0 + 1]);
            B3[f][1] = packbf(W1[qr * 32 + k0 + 8], W1[qr * 32 + k0 + 9]);
        } else {
            B3[f][0] = 0u;
            B3[f][1] = 0u;
        }
    }

    const int warps_per_cta = NTHREADS / 32;
    const int total_warps = gridDim.x * warps_per_cta;
    const int gw = blockIdx.x * warps_per_cta + wid;
    const float zz[4] = {0.0f, 0.0f, 0.0f, 0.0f};

    // Single-tile clamped path (tail only; correctness, not speed).
    auto do_tile_clamped = [&](int base) {
        const int r0 = base + qr;
        const int r1 = base + qr + 8;
        const int r0c = min(r0, n - 1);
        const int r1c = min(r1, n - 1);
        const float vy1a = y1[r0c], vy1b = y1[r1c];
        const float vy2a = y2[r0c], vy2b = y2[r1c];
        const unsigned y1pa = cvtpack(vy1a, vy1a), y2pa = cvtpack(vy2a, vy2a);
        const unsigned y1pb = cvtpack(vy1b, vy1b), y2pb = cvtpack(vy2b, vy2b);

        unsigned h[2][4];
#pragma unroll
        for (int j = 0; j < 4; j++) {
            unsigned p0 = bfma2(y1pa, w10p[j], bfma2(y2pa, w11p[j], b1p[j]));
            unsigned p1 = bfma2(y1pb, w10p[j], bfma2(y2pb, w11p[j], b1p[j]));
            h[0][j] = bfma2(tanh2(p0), h05, h05);
            h[1][j] = bfma2(tanh2(p1), h05, h05);
        }
        unsigned a0[4] = {h[0][0], h[1][0], h[0][1], h[1][1]};
        unsigned a1[4] = {h[0][2], h[1][2], h[0][3], h[1][3]};
        float d[4][4];
#pragma unroll
        for (int j = 0; j < 4; j++) {
            mma16816(d[j], a0, B1[j][0], zz);
            mma16816(d[j], a1, B1[j][1], d[j]);
        }
        unsigned g[2][4];
#pragma unroll
        for (int j = 0; j < 4; j++) {
#pragma unroll
            for (int s = 0; s < 2; s++) {
                unsigned pr = badd2(cvtpack(d[j][2 * s], d[j][2 * s + 1]), b2p[j]);
                unsigned h2 = bfma2(tanh2(pr), h05, h05);
                unsigned tm = bmul2(h2, w3p[j]);
                g[s][j] = bfma2(bneg2(h2), tm, tm);
            }
        }
        unsigned ga0[4] = {g[0][0], g[1][0], g[0][1], g[1][1]};
        unsigned ga1[4] = {g[0][2], g[1][2], g[0][3], g[1][3]};
#pragma unroll
        for (int j = 0; j < 4; j++) {
            mma16816(d[j], ga0, B2[j][0], zz);
            mma16816(d[j], ga1, B2[j][1], d[j]);
        }
        unsigned dp[2][4];
#pragma unroll
        for (int j = 0; j < 4; j++) {
#pragma unroll
            for (int s = 0; s < 2; s++) {
                unsigned hp = bfma2(bneg2(h[s][j]), h[s][j], h[s][j]);
                dp[s][j] = bmul2(cvtpack(d[j][2 * s], d[j][2 * s + 1]), hp);
            }
        }
        unsigned da0[4] = {dp[0][0], dp[1][0], dp[0][1], dp[1][1]};
        unsigned da1[4] = {dp[0][2], dp[1][2], dp[0][3], dp[1][3]};
        float cx[4] = {0.0f, 0.0f, 0.0f, 0.0f};
        if (tg == 0) {
            cx[0] = x1[r0c];
            cx[1] = x2[r0c];
            cx[2] = x1[r1c];
            cx[3] = x2[r1c];
        }
        float d3[4];
        mma16816(d3, da0, B3[0], cx);
        mma16816(d3, da1, B3[1], d3);
        if (tg == 0) {
            if (r0 < n) {
                float4 o;
                o.x = d3[0]; o.y = d3[1]; o.z = vy1a; o.w = vy2a;
                reinterpret_cast<float4*>(out)[r0] = o;
            }
            if (r1 < n) {
                float4 o;
                o.x = d3[2]; o.y = d3[3]; o.z = vy1b; o.w = vy2b;
                reinterpret_cast<float4*>(out)[r1] = o;
            }
        }
    };

    for (int pair = gw; pair < npairs; pair += total_warps) {
        const int base = pair * 32;

        if (base + 32 <= n) {
            // =========== fast path: two independent tiles, interleaved ==========
            int r0[2], r1[2];
            float vy1a[2], vy1b[2], vy2a[2], vy2b[2];
#pragma unroll
            for (int t = 0; t < 2; t++) {
                r0[t] = base + 16 * t + qr;
                r1[t] = r0[t] + 8;
                vy1a[t] = y1[r0[t]];
                vy1b[t] = y1[r1[t]];
                vy2a[t] = y2[r0[t]];
                vy2b[t] = y2[r1[t]];
            }

            // ---- layer 1 ----
            unsigned h[2][2][4];
#pragma unroll
            for (int t = 0; t < 2; t++) {
                const unsigned y1pa = cvtpack(vy1a[t], vy1a[t]);
                const unsigned y2pa = cvtpack(vy2a[t], vy2a[t]);
                const unsigned y1pb = cvtpack(vy1b[t], vy1b[t]);
                const unsigned y2pb = cvtpack(vy2b[t], vy2b[t]);
#pragma unroll
                for (int j = 0; j < 4; j++) {
                    unsigned p0 = bfma2(y1pa, w10p[j], bfma2(y2pa, w11p[j], b1p[j]));
                    unsigned p1 = bfma2(y1pb, w10p[j], bfma2(y2pb, w11p[j], b1p[j]));
                    h[t][0][j] = bfma2(tanh2(p0), h05, h05);
                    h[t][1][j] = bfma2(tanh2(p1), h05, h05);
                }
            }

            // ---- MMA1: 0.5*(h1 @ W2) ----
            float d[2][4][4];
#pragma unroll
            for (int t = 0; t < 2; t++) {
                unsigned a0[4] = {h[t][0][0], h[t][1][0], h[t][0][1], h[t][1][1]};
                unsigned a1[4] = {h[t][0][2], h[t][1][2], h[t][0][3], h[t][1][3]};
#pragma unroll
                for (int j = 0; j < 4; j++) {
                    mma16816(d[t][j], a0, B1[j][0], zz);
                    mma16816(d[t][j], a1, B1[j][1], d[t][j]);
                }
            }

            // ---- layer 2 elementwise ----
            unsigned g[2][2][4];
#pragma unroll
            for (int t = 0; t < 2; t++) {
#pragma unroll
                for (int j = 0; j < 4; j++) {
#pragma unroll
                    for (int s = 0; s < 2; s++) {
                        unsigned pr = badd2(cvtpack(d[t][j][2 * s], d[t][j][2 * s + 1]), b2p[j]);
                        unsigned h2 = bfma2(tanh2(pr), h05, h05);
                        unsigned tm = bmul2(h2, w3p[j]);
                        g[t][s][j] = bfma2(bneg2(h2), tm, tm);
                    }
                }
            }

            // ---- MMA2: d1 = g2 @ W2^T ----
#pragma unroll
            for (int t = 0; t < 2; t++) {
                unsigned ga0[4] = {g[t][0][0], g[t][1][0], g[t][0][1], g[t][1][1]};
                unsigned ga1[4] = {g[t][0][2], g[t][1][2], g[t][0][3], g[t][1][3]};
#pragma unroll
                for (int j = 0; j < 4; j++) {
                    mma16816(d[t][j], ga0, B2[j][0], zz);
                    mma16816(d[t][j], ga1, B2[j][1], d[t][j]);
                }
            }

            // ---- dp = d1 * h1 * (1-h1); MMA3; store ----
            float d3[2][4];
#pragma unroll
            for (int t = 0; t < 2; t++) {
                unsigned dp[2][4];
#pragma unroll
                for (int j = 0; j < 4; j++) {
#pragma unroll
                    for (int s = 0; s < 2; s++) {
                        unsigned hp = bfma2(bneg2(h[t][s][j]), h[t][s][j], h[t][s][j]);
                        dp[s][j] = bmul2(cvtpack(d[t][j][2 * s], d[t][j][2 * s + 1]), hp);
                    }
                }
                unsigned da0[4] = {dp[0][0], dp[1][0], dp[0][1], dp[1][1]};
                unsigned da1[4] = {dp[0][2], dp[1][2], dp[0][3], dp[1][3]};
                float cx[4] = {0.0f, 0.0f, 0.0f, 0.0f};
                if (tg == 0) {
                    cx[0] = x1[r0[t]];
                    cx[1] = x2[r0[t]];
                    cx[2] = x1[r1[t]];
                    cx[3] = x2[r1[t]];
                }
                mma16816(d3[t], da0, B3[0], cx);
                mma16816(d3[t], da1, B3[1], d3[t]);
            }

            if (tg == 0) {
#pragma unroll
                for (int t = 0; t < 2; t++) {
                    float4 o;
                    o.x = d3[t][0]; o.y = d3[t][1]; o.z = vy1a[t]; o.w = vy2a[t];
                    reinterpret_cast<float4*>(out)[r0[t]] = o;
                    o.x = d3[t][2]; o.y = d3[t][3]; o.z = vy1b[t]; o.w = vy2b[t];
                    reinterpret_cast<float4*>(out)[r1[t]] = o;
                }
            }
        } else {
            // =========== tail: clamped single tiles ==========
            if (base < n) do_tile_clamped(base);
            if (base + 16 < n) do_tile_clamped(base + 16);
        }
    }
}

extern "C" void kernel_launch(void* const* d_in, const int* in_sizes, int n_in,
                              void* d_out, int out_size) {
    const float* x1 = (const float*)d_in[0];
    const float* x2 = (const float*)d_in[1];
    const float* y1 = (const float*)d_in[2];
    const float* y2 = (const float*)d_in[3];
    const float* W1 = (const float*)d_in[4];
    const float* b1 = (const float*)d_in[5];
    const float* W2 = (const float*)d_in[6];
    const float* b2 = (const float*)d_in[7];
    const float* W3 = (const float*)d_in[8];
    float* out = (float*)d_out;

    int n = in_sizes[0];
    int npairs = (n + 31) / 32;

    int per_sm = 0;
    cudaOccupancyMaxActiveBlocksPerMultiprocessor(&per_sm, mlp_grad_kernel,
                                                  NTHREADS, 0);
    if (per_sm < 1) per_sm = 1;
    int sms = 0;
    cudaDeviceGetAttribute(&sms, cudaDevAttrMultiProcessorCount, 0);
    if (sms <= 0) sms = 148;

    int grid = per_sm * sms;
    int max_grid = (npairs + (NTHREADS / 32) - 1) / (NTHREADS / 32);
    if (grid > max_grid) grid = max_grid;

    mlp_grad_kernel<<<grid, NTHREADS>>>(x1, x2, y1, y2, W1, b1, W2, b2, W3, out,
                                        n, npairs);
}